// round 3
// baseline (speedup 1.0000x reference)
#include <cuda_runtime.h>
#include <cuda_bf16.h>

// Problem constants
#define BATCH 32
#define KSAMP 16
#define NEXP  312
#define D_IN  312
#define H1    1024
#define H2    2048
#define D_OUT 128
#define ROWS  17          // 1 query + 16 samples
#define RP    18          // padded rows (even, for f32x2 pairing)
#define ROWP  9           // row pairs
#define INV_T 8.3333333333333333f   // 1/0.12

typedef unsigned long long u64;

// ---------------- scratch (no allocations allowed) ----------------
__device__ float g_h1[(size_t)BATCH * ROWS * H1];                 // 2.2 MB
__device__ float g_h2[(size_t)BATCH * ROWS * H2];                 // 4.5 MB
__device__ float g_p[(size_t)32 * BATCH * ROWS * D_OUT];          // 8.9 MB (32 split-K slots)

// ---------------- f32x2 helpers ----------------
__device__ __forceinline__ u64 pack2(float lo, float hi) {
    u64 r; asm("mov.b64 %0, {%1, %2};" : "=l"(r) : "f"(lo), "f"(hi)); return r;
}
__device__ __forceinline__ float2 unpack2(u64 v) {
    float2 f; asm("mov.b64 {%0, %1}, %2;" : "=f"(f.x), "=f"(f.y) : "l"(v)); return f;
}
__device__ __forceinline__ u64 ffma2(u64 a, u64 b, u64 c) {
    u64 d; asm("fma.rn.f32x2 %0, %1, %2, %3;" : "=l"(d) : "l"(a), "l"(b), "l"(c)); return d;
}

// ---------------- core: 18 rows (9 f32x2 pairs) x 4 cols, C inner-dim steps ----
// sXT: transposed input tile, layout [c][RP] floats, 8B-aligned pairs.
// Wp:  weight base already offset to (row 0, col j0); row stride LDW floats.
template<int C, int LDW>
__device__ __forceinline__ void mlp_core(const float* __restrict__ sXT,
                                         const float* __restrict__ Wp,
                                         u64 acc[ROWP][4]) {
    const float4* __restrict__ w4 = reinterpret_cast<const float4*>(Wp);
    constexpr int WSTRIDE = LDW / 4;
#pragma unroll 4
    for (int c = 0; c < C; ++c) {
        float4 w = w4[c * WSTRIDE];                     // LDG.128 (unique weight bytes)
        u64 w0 = pack2(w.x, w.x);
        u64 w1 = pack2(w.y, w.y);
        u64 w2 = pack2(w.z, w.z);
        u64 w3 = pack2(w.w, w.w);
        const u64* __restrict__ xp = reinterpret_cast<const u64*>(sXT + c * RP);
#pragma unroll
        for (int rp = 0; rp < ROWP; ++rp) {
            u64 xx = xp[rp];                            // LDS.64, broadcast across warp
            acc[rp][0] = ffma2(xx, w0, acc[rp][0]);
            acc[rp][1] = ffma2(xx, w1, acc[rp][1]);
            acc[rp][2] = ffma2(xx, w2, acc[rp][2]);
            acc[rp][3] = ffma2(xx, w3, acc[rp][3]);
        }
    }
}

__device__ __forceinline__ void zero_acc(u64 acc[ROWP][4]) {
#pragma unroll
    for (int rp = 0; rp < ROWP; ++rp)
#pragma unroll
        for (int u = 0; u < 4; ++u) acc[rp][u] = 0ull;
}

// epilogue with bias + ReLU, writes 17 real rows, row stride N
template<int N>
__device__ __forceinline__ void store_relu17(u64 acc[ROWP][4],
                                             const float* __restrict__ bias_j0,
                                             float* __restrict__ out_bj0) {
    float4 bv = *reinterpret_cast<const float4*>(bias_j0);
#pragma unroll
    for (int rp = 0; rp < ROWP; ++rp) {
        float2 c0 = unpack2(acc[rp][0]);
        float2 c1 = unpack2(acc[rp][1]);
        float2 c2 = unpack2(acc[rp][2]);
        float2 c3 = unpack2(acc[rp][3]);
        float4 o0;
        o0.x = fmaxf(c0.x + bv.x, 0.f);
        o0.y = fmaxf(c1.x + bv.y, 0.f);
        o0.z = fmaxf(c2.x + bv.z, 0.f);
        o0.w = fmaxf(c3.x + bv.w, 0.f);
        *reinterpret_cast<float4*>(out_bj0 + (size_t)(2 * rp) * N) = o0;
        if (2 * rp + 1 < ROWS) {
            float4 o1;
            o1.x = fmaxf(c0.y + bv.x, 0.f);
            o1.y = fmaxf(c1.y + bv.y, 0.f);
            o1.z = fmaxf(c2.y + bv.z, 0.f);
            o1.w = fmaxf(c3.y + bv.w, 0.f);
            *reinterpret_cast<float4*>(out_bj0 + (size_t)(2 * rp + 1) * N) = o1;
        }
    }
}

// ---------------- layer 1: gather rows + [17x312] @ [312x1024] ----------------
__global__ void __launch_bounds__(128) l1_kernel(const float* __restrict__ v2s,
                                                 const int* __restrict__ tar,
                                                 const int* __restrict__ sidx,
                                                 const float* __restrict__ W,
                                                 const float* __restrict__ bias) {
    constexpr int C = D_IN, N = H1, BPB = 2, TPB = 128;
    extern __shared__ float sXT[];          // [C][RP]
    __shared__ int sRow[ROWS];
    const int b = blockIdx.x / BPB;
    const int jb = blockIdx.x % BPB;
    const int tid = threadIdx.x;
    if (tid < ROWS) sRow[tid] = (tid == 0) ? b : sidx[b * KSAMP + tid - 1];
    __syncthreads();
    for (int idx = tid; idx < RP * C; idx += TPB) {
        int r = idx / C, c = idx - r * C;
        sXT[c * RP + r] = (r < ROWS) ? v2s[(size_t)sRow[r] * C + c] : 0.f;
    }
    __syncthreads();
    const int e = tar[b];
    const int j0 = jb * (TPB * 4) + tid * 4;
    u64 acc[ROWP][4];
    zero_acc(acc);
    mlp_core<C, N>(sXT, W + (size_t)e * C * N + j0, acc);
    store_relu17<N>(acc, bias + (size_t)e * N + j0, g_h1 + (size_t)b * ROWS * N + j0);
}

// ---------------- layer 2: [17x1024] @ [1024x2048] ----------------
__global__ void __launch_bounds__(128) l2_kernel(const int* __restrict__ tar,
                                                 const float* __restrict__ W,
                                                 const float* __restrict__ bias) {
    constexpr int C = H1, N = H2, BPB = 4, TPB = 128;
    extern __shared__ float sXT[];          // [C][RP] = 73728 B
    const int b = blockIdx.x / BPB;
    const int jb = blockIdx.x % BPB;
    const int tid = threadIdx.x;
    const float* __restrict__ in = g_h1 + (size_t)b * ROWS * C;
    for (int idx = tid; idx < RP * C; idx += TPB) {
        int r = idx >> 10, c = idx & (C - 1);
        sXT[c * RP + r] = (r < ROWS) ? in[(size_t)r * C + c] : 0.f;
    }
    __syncthreads();
    const int e = tar[b];
    const int j0 = jb * (TPB * 4) + tid * 4;
    u64 acc[ROWP][4];
    zero_acc(acc);
    mlp_core<C, N>(sXT, W + (size_t)e * C * N + j0, acc);
    store_relu17<N>(acc, bias + (size_t)e * N + j0, g_h2 + (size_t)b * ROWS * N + j0);
}

// ---------------- layer 3 split-K: [17x2048] @ [2048x128], 32 partial slots ----
__global__ void __launch_bounds__(128) l3_kernel(const int* __restrict__ tar,
                                                 const float* __restrict__ W) {
    constexpr int CCH = 256, N = D_OUT, NSB = 8, TPB = 128;
    extern __shared__ float sXT[];          // [CCH][RP]
    const int b = blockIdx.x / NSB;
    const int s = blockIdx.x % NSB;
    const int tid = threadIdx.x;
    const float* __restrict__ in = g_h2 + (size_t)b * ROWS * H2 + s * CCH;
    for (int idx = tid; idx < RP * CCH; idx += TPB) {
        int r = idx >> 8, c = idx & (CCH - 1);
        sXT[c * RP + r] = (r < ROWS) ? in[(size_t)r * H2 + c] : 0.f;
    }
    __syncthreads();
    const int e = tar[b];
    const int w = tid >> 5;                 // warp handles 64-c subchunk
    const int lane = tid & 31;
    const int j0 = lane * 4;
    const float* Wp = W + ((size_t)e * H2 + (size_t)s * CCH + w * 64) * N + j0;
    u64 acc[ROWP][4];
    zero_acc(acc);
    mlp_core<64, N>(sXT + (w * 64) * RP, Wp, acc);
    const int sp = s * 4 + w;               // 0..31 partial slot
    float* __restrict__ outp = g_p + (((size_t)sp * BATCH + b) * ROWS) * N + j0;
#pragma unroll
    for (int rp = 0; rp < ROWP; ++rp) {
        float2 c0 = unpack2(acc[rp][0]);
        float2 c1 = unpack2(acc[rp][1]);
        float2 c2 = unpack2(acc[rp][2]);
        float2 c3 = unpack2(acc[rp][3]);
        float4 o0 = {c0.x, c1.x, c2.x, c3.x};
        *reinterpret_cast<float4*>(outp + (size_t)(2 * rp) * N) = o0;
        if (2 * rp + 1 < ROWS) {
            float4 o1 = {c0.y, c1.y, c2.y, c3.y};
            *reinterpret_cast<float4*>(outp + (size_t)(2 * rp + 1) * N) = o1;
        }
    }
}

// ---------------- reduce partials + bias + ReLU + logits ----------------
__global__ void __launch_bounds__(128) logits_kernel(const int* __restrict__ tar,
                                                     const float* __restrict__ b3,
                                                     float* __restrict__ out) {
    __shared__ float sQK[ROWS * D_OUT];
    const int b = blockIdx.x;
    const int tid = threadIdx.x;            // one column each
    const int e = tar[b];
    const float bv = b3[(size_t)e * D_OUT + tid];
    for (int r = 0; r < ROWS; ++r) {
        float v = bv;
#pragma unroll 8
        for (int sp = 0; sp < 32; ++sp)
            v += g_p[(((size_t)sp * BATCH + b) * ROWS + r) * D_OUT + tid];
        sQK[r * D_OUT + tid] = fmaxf(v, 0.f);
    }
    __syncthreads();
    // 16 logits: thread groups of 8 per k
    const int k = tid >> 3;                 // 0..15
    const int l = tid & 7;
    float s = 0.f;
#pragma unroll
    for (int j = 0; j < D_OUT / 8; ++j) {
        int col = l + j * 8;
        s += sQK[col] * sQK[(k + 1) * D_OUT + col];
    }
    s += __shfl_xor_sync(0xFFFFFFFFu, s, 1);
    s += __shfl_xor_sync(0xFFFFFFFFu, s, 2);
    s += __shfl_xor_sync(0xFFFFFFFFu, s, 4);
    if (l == 0) out[b * KSAMP + k] = s * INV_T;
}

// ---------------- launch ----------------
extern "C" void kernel_launch(void* const* d_in, const int* in_sizes, int n_in,
                              void* d_out, int out_size) {
    const float* v2s  = (const float*)d_in[0];
    const float* W1   = (const float*)d_in[1];
    const float* b1   = (const float*)d_in[2];
    const float* W2   = (const float*)d_in[3];
    const float* b2   = (const float*)d_in[4];
    const float* W3   = (const float*)d_in[5];
    const float* b3   = (const float*)d_in[6];
    const int*   tar  = (const int*)d_in[7];
    const int*   sidx = (const int*)d_in[8];
    float* out = (float*)d_out;

    static_assert(RP * H1 * 4 == 73728, "smem size");
    cudaFuncSetAttribute(l2_kernel, cudaFuncAttributeMaxDynamicSharedMemorySize, RP * H1 * 4);

    l1_kernel<<<BATCH * 2, 128, RP * D_IN * 4>>>(v2s, tar, sidx, W1, b1);
    l2_kernel<<<BATCH * 4, 128, RP * H1 * 4>>>(tar, W2, b2);
    l3_kernel<<<BATCH * 8, 128, RP * 256 * 4>>>(tar, W3);
    logits_kernel<<<BATCH, 128>>>(tar, b3, out);
}

// round 4
// speedup vs baseline: 3.4252x; 3.4252x over previous
#include <cuda_runtime.h>
#include <cuda_bf16.h>

// ---------------- problem constants ----------------
#define BATCH 32
#define KSAMP 16
#define D_IN  312
#define H1    1024
#define H2    2048
#define D_OUT 128
#define ROWS  17          // 1 query + 16 samples
#define ROWP  9           // row pairs (rows padded to 18; row 17 computed, never stored)
#define RPAD  20          // smem row stride in floats (80B -> 16B-aligned pair loads)
#define INV_T 8.3333333333333333f   // 1/0.12

// ---------------- decomposition ----------------
#define KCH1 4            // L1 K-split (chunks of 78)
#define CCH1 78
#define CB1  4            // L1 col blocks (128 thr x 2 cols = 256 cols each)
#define KCH2 4            // L2 K-split (chunks of 256)
#define CCH2 256
#define CB2  8            // L2 col blocks
#define KCH3 16           // L3 K-split (chunks of 128)
#define CCH3 128

typedef unsigned long long u64;

// ---------------- scratch (no allocations allowed) ----------------
__device__ float g_h1p[(size_t)KCH1 * BATCH * ROWS * H1];    // 8.9 MB  L1 partials
__device__ float g_h2p[(size_t)KCH2 * BATCH * ROWS * H2];    // 17.8 MB L2 partials
__device__ float g_p  [(size_t)KCH3 * BATCH * ROWS * D_OUT]; // 4.45 MB L3 partials

// ---------------- f32x2 helpers ----------------
__device__ __forceinline__ u64 pack2(float lo, float hi) {
    u64 r; asm("mov.b64 %0, {%1, %2};" : "=l"(r) : "f"(lo), "f"(hi)); return r;
}
__device__ __forceinline__ float2 unpack2(u64 v) {
    float2 f; asm("mov.b64 {%0, %1}, %2;" : "=f"(f.x), "=f"(f.y) : "l"(v)); return f;
}
__device__ __forceinline__ u64 ffma2(u64 a, u64 b, u64 c) {
    u64 d; asm("fma.rn.f32x2 %0, %1, %2, %3;" : "=l"(d) : "l"(a), "l"(b), "l"(c)); return d;
}

template<int CPT>
__device__ __forceinline__ void zacc(u64 acc[ROWP][CPT]) {
#pragma unroll
    for (int rp = 0; rp < ROWP; ++rp)
#pragma unroll
        for (int q = 0; q < CPT; ++q) acc[rp][q] = 0ull;
}

// ---------------- core GEMM loop ----------------
// sXT: transposed input tile [c][RPAD] floats (16B-aligned rows).
// Wp:  weight base at (chunk row 0, this thread's col j0); row stride LDW floats.
template<int CCH, int LDW, int CPT>
__device__ __forceinline__ void core(const float* __restrict__ sXT,
                                     const float* __restrict__ Wp,
                                     u64 acc[ROWP][CPT]) {
#pragma unroll 4
    for (int c = 0; c < CCH; ++c) {
        u64 wp[CPT];
        if (CPT == 2) {
            float2 w = __ldg(reinterpret_cast<const float2*>(Wp + (size_t)c * LDW));
            wp[0] = pack2(w.x, w.x);
            wp[1] = pack2(w.y, w.y);
        } else {
            float w = __ldg(Wp + (size_t)c * LDW);
            wp[0] = pack2(w, w);
        }
        const float* xb = sXT + c * RPAD;
        ulonglong2 x01 = *reinterpret_cast<const ulonglong2*>(xb);      // LDS.128
        ulonglong2 x23 = *reinterpret_cast<const ulonglong2*>(xb + 4);
        ulonglong2 x45 = *reinterpret_cast<const ulonglong2*>(xb + 8);
        ulonglong2 x67 = *reinterpret_cast<const ulonglong2*>(xb + 12);
        u64 x8 = *reinterpret_cast<const u64*>(xb + 16);                // LDS.64
        u64 xs[ROWP] = {x01.x, x01.y, x23.x, x23.y, x45.x, x45.y, x67.x, x67.y, x8};
#pragma unroll
        for (int rp = 0; rp < ROWP; ++rp)
#pragma unroll
            for (int q = 0; q < CPT; ++q)
                acc[rp][q] = ffma2(xs[rp], wp[q], acc[rp][q]);
    }
}

// raw partial store, 17 real rows, row stride N
template<int N, int CPT>
__device__ __forceinline__ void store_partial(u64 acc[ROWP][CPT], float* __restrict__ out) {
#pragma unroll
    for (int rp = 0; rp < ROWP; ++rp) {
        float2 c0 = unpack2(acc[rp][0]);
        if (CPT == 2) {
            float2 c1 = unpack2(acc[rp][1]);
            *reinterpret_cast<float2*>(out + (size_t)(2 * rp) * N) = make_float2(c0.x, c1.x);
            if (2 * rp + 1 < ROWS)
                *reinterpret_cast<float2*>(out + (size_t)(2 * rp + 1) * N) = make_float2(c0.y, c1.y);
        } else {
            out[(size_t)(2 * rp) * N] = c0.x;
            if (2 * rp + 1 < ROWS) out[(size_t)(2 * rp + 1) * N] = c0.y;
        }
    }
}

// ---------------- layer 1: gather + [17x312]@[312x1024], split-K x4 ----------------
__global__ void __launch_bounds__(128) l1_kernel(const float* __restrict__ v2s,
                                                 const int* __restrict__ tar,
                                                 const int* __restrict__ sidx,
                                                 const float* __restrict__ W1) {
    __shared__ __align__(16) float sXT[CCH1 * RPAD];
    __shared__ int sRow[ROWS];
    const int tid = threadIdx.x;
    const int cb = blockIdx.x % CB1;
    const int kc = (blockIdx.x / CB1) % KCH1;
    const int b  = blockIdx.x / (CB1 * KCH1);
    if (tid < ROWS) sRow[tid] = (tid == 0) ? b : sidx[b * KSAMP + tid - 1];
    __syncthreads();
    const int c0 = kc * CCH1;
    for (int idx = tid; idx < CCH1 * RPAD; idx += 128) {
        int r = idx / CCH1, c = idx - r * CCH1;
        sXT[c * RPAD + r] = (r < ROWS) ? v2s[(size_t)sRow[r] * D_IN + c0 + c] : 0.f;
    }
    __syncthreads();
    const int e = tar[b];
    const int j0 = (cb * 128 + tid) * 2;
    u64 acc[ROWP][2];
    zacc<2>(acc);
    core<CCH1, H1, 2>(sXT, W1 + ((size_t)e * D_IN + c0) * H1 + j0, acc);
    store_partial<H1, 2>(acc, g_h1p + (((size_t)kc * BATCH + b) * ROWS) * H1 + j0);
}

// ---------------- layer 2: [17x1024]@[1024x2048], split-K x4 ----------------
// input = relu(sum of 4 L1 partial slots + b1), built during smem fill
__global__ void __launch_bounds__(128) l2_kernel(const int* __restrict__ tar,
                                                 const float* __restrict__ W2,
                                                 const float* __restrict__ b1) {
    __shared__ __align__(16) float sXT[CCH2 * RPAD];   // 20 KB
    const int tid = threadIdx.x;
    const int cb = blockIdx.x % CB2;
    const int kc = (blockIdx.x / CB2) % KCH2;
    const int b  = blockIdx.x / (CB2 * KCH2);
    const int e  = tar[b];
    const int c0 = kc * CCH2;
    const size_t SL = (size_t)BATCH * ROWS * H1;
    for (int idx = tid; idx < CCH2 * RPAD; idx += 128) {
        int r = idx / CCH2, c = idx & (CCH2 - 1);
        float v = 0.f;
        if (r < ROWS) {
            int cg = c0 + c;
            size_t off = ((size_t)b * ROWS + r) * H1 + cg;
            float s = g_h1p[off] + g_h1p[SL + off] + g_h1p[2 * SL + off] + g_h1p[3 * SL + off];
            v = fmaxf(s + b1[(size_t)e * H1 + cg], 0.f);
        }
        sXT[c * RPAD + r] = v;
    }
    __syncthreads();
    const int j0 = (cb * 128 + tid) * 2;
    u64 acc[ROWP][2];
    zacc<2>(acc);
    core<CCH2, H2, 2>(sXT, W2 + ((size_t)e * H1 + c0) * H2 + j0, acc);
    store_partial<H2, 2>(acc, g_h2p + (((size_t)kc * BATCH + b) * ROWS) * H2 + j0);
}

// ---------------- layer 3: [17x2048]@[2048x128], split-K x16 ----------------
// input = relu(sum of 4 L2 partial slots + b2), built during smem fill
__global__ void __launch_bounds__(128) l3_kernel(const int* __restrict__ tar,
                                                 const float* __restrict__ W3,
                                                 const float* __restrict__ b2) {
    __shared__ __align__(16) float sXT[CCH3 * RPAD];   // 10 KB
    const int tid = threadIdx.x;
    const int kc = blockIdx.x % KCH3;
    const int b  = blockIdx.x / KCH3;
    const int e  = tar[b];
    const int c0 = kc * CCH3;
    const size_t SL = (size_t)BATCH * ROWS * H2;
    for (int idx = tid; idx < CCH3 * RPAD; idx += 128) {
        int r = idx / CCH3, c = idx & (CCH3 - 1);
        float v = 0.f;
        if (r < ROWS) {
            int cg = c0 + c;
            size_t off = ((size_t)b * ROWS + r) * H2 + cg;
            float s = g_h2p[off] + g_h2p[SL + off] + g_h2p[2 * SL + off] + g_h2p[3 * SL + off];
            v = fmaxf(s + b2[(size_t)e * H2 + cg], 0.f);
        }
        sXT[c * RPAD + r] = v;
    }
    __syncthreads();
    u64 acc[ROWP][1];
    zacc<1>(acc);
    core<CCH3, D_OUT, 1>(sXT, W3 + ((size_t)e * H2 + c0) * D_OUT + tid, acc);
    store_partial<D_OUT, 1>(acc, g_p + (((size_t)kc * BATCH + b) * ROWS) * D_OUT + tid);
}

// ---------------- reduce 16 L3 partials + b3 + relu + logits ----------------
__global__ void __launch_bounds__(256) logits_kernel(const int* __restrict__ tar,
                                                     const float* __restrict__ b3,
                                                     float* __restrict__ out) {
    __shared__ float sQK[ROWS * D_OUT];
    const int b = blockIdx.x;
    const int tid = threadIdx.x;
    const int e = tar[b];
    const size_t SL = (size_t)BATCH * ROWS * D_OUT;
    for (int idx = tid; idx < ROWS * D_OUT; idx += 256) {
        int r = idx >> 7, c = idx & 127;
        float v = b3[(size_t)e * D_OUT + c];
        size_t off = ((size_t)b * ROWS + r) * D_OUT + c;
#pragma unroll
        for (int s = 0; s < KCH3; ++s) v += g_p[s * SL + off];
        sQK[idx] = fmaxf(v, 0.f);
    }
    __syncthreads();
    // 16 logits: 16 lanes per k, 8 columns each
    const int k = tid >> 4;
    const int l = tid & 15;
    float s = 0.f;
#pragma unroll
    for (int j = 0; j < D_OUT / 16; ++j) {
        int col = l + j * 16;
        s += sQK[col] * sQK[(k + 1) * D_OUT + col];
    }
    s += __shfl_xor_sync(0xFFFFFFFFu, s, 1);
    s += __shfl_xor_sync(0xFFFFFFFFu, s, 2);
    s += __shfl_xor_sync(0xFFFFFFFFu, s, 4);
    s += __shfl_xor_sync(0xFFFFFFFFu, s, 8);
    if (l == 0) out[b * KSAMP + k] = s * INV_T;
}

// ---------------- launch ----------------
extern "C" void kernel_launch(void* const* d_in, const int* in_sizes, int n_in,
                              void* d_out, int out_size) {
    const float* v2s  = (const float*)d_in[0];
    const float* W1   = (const float*)d_in[1];
    const float* b1   = (const float*)d_in[2];
    const float* W2   = (const float*)d_in[3];
    const float* b2   = (const float*)d_in[4];
    const float* W3   = (const float*)d_in[5];
    const float* b3   = (const float*)d_in[6];
    const int*   tar  = (const int*)d_in[7];
    const int*   sidx = (const int*)d_in[8];
    float* out = (float*)d_out;

    l1_kernel<<<BATCH * KCH1 * CB1, 128>>>(v2s, tar, sidx, W1);   // 512 blocks
    l2_kernel<<<BATCH * KCH2 * CB2, 128>>>(tar, W2, b1);          // 1024 blocks
    l3_kernel<<<BATCH * KCH3, 128>>>(tar, W3, b2);                // 512 blocks
    logits_kernel<<<BATCH, 256>>>(tar, b3, out);                  // 32 blocks
}